// round 4
// baseline (speedup 1.0000x reference)
#include <cuda_runtime.h>
#include <cuda_bf16.h>
#include <cstdint>

#define N_NODES 100000
#define N_EDGES 1000000
#define IN_CH   128
#define OUT_CH  128
#define T_DIM   64
#define AGG_W   192   // 128 (x-sum) + 64 (tf-sum)

// ---------------- device scratch ----------------
__device__ __align__(16) float g_agg[(size_t)N_NODES * AGG_W];
__device__ __align__(16) float g_deg[N_NODES];
__device__ __align__(16) float g_Wt[320 * 128];   // combined transposed weight [k][o]
__device__ __align__(16) float g_cb[128];         // W_T_b + T_b
__device__ int g_idx_is64;

// ---------------- helpers ----------------
__device__ __forceinline__ void red_add_v4(float* p, float4 v) {
    unsigned long long gp = __cvta_generic_to_global((void*)p);
    asm volatile("red.global.add.v4.f32 [%0], {%1,%2,%3,%4};"
                 :: "l"(gp), "f"(v.x), "f"(v.y), "f"(v.z), "f"(v.w)
                 : "memory");
}
__device__ __forceinline__ unsigned long long pack2(float lo, float hi) {
    unsigned long long r;
    asm("mov.b64 %0, {%1, %2};" : "=l"(r) : "f"(lo), "f"(hi));
    return r;
}
__device__ __forceinline__ void fma2(unsigned long long& acc, unsigned long long a,
                                     unsigned long long b) {
    asm("fma.rn.f32x2 %0, %1, %2, %0;" : "+l"(acc) : "l"(a), "l"(b));
}

// ---------------- kernel 0: detect edge_index dtype ----------------
__global__ void detect_kernel(const int* __restrict__ ei_raw) {
    __shared__ int any_nonzero;
    if (threadIdx.x == 0) any_nonzero = 0;
    __syncthreads();
    for (int i = threadIdx.x; i < 4096; i += blockDim.x)
        if (ei_raw[2 * i + 1] != 0) any_nonzero = 1;
    __syncthreads();
    if (threadIdx.x == 0) g_idx_is64 = (any_nonzero == 0);
}

__device__ __forceinline__ int load_idx(const void* ei_raw, size_t pos) {
    if (g_idx_is64) return (int)__ldg(&((const long long*)ei_raw)[pos]);
    return __ldg(&((const int*)ei_raw)[pos]);
}

// ---------------- kernel 1: build combined transposed weights ----------------
__global__ void prep_kernel(const float* __restrict__ Wsw,
                            const float* __restrict__ Wtw,
                            const float* __restrict__ Tw,
                            const float* __restrict__ Wtb,
                            const float* __restrict__ Tb) {
    int tid = blockIdx.x * blockDim.x + threadIdx.x;
    if (tid < 320 * 128) {
        int k = tid >> 7;
        int o = tid & 127;
        float v;
        if (k < 128)       v = Wsw[o * 128 + k];
        else if (k < 256)  v = Wtw[o * 128 + (k - 128)];
        else               v = Tw[o * 64 + (k - 256)];
        g_Wt[k * 128 + o] = v;
    }
    if (tid < 128) g_cb[tid] = Wtb[tid] + Tb[tid];
}

// ---------------- kernel 2: zero accumulators ----------------
__global__ void zero_kernel() {
    const size_t n4_agg = (size_t)N_NODES * AGG_W / 4;
    const size_t n4_deg = N_NODES / 4;
    float4 z = make_float4(0.f, 0.f, 0.f, 0.f);
    size_t stride = (size_t)gridDim.x * blockDim.x;
    for (size_t i = blockIdx.x * (size_t)blockDim.x + threadIdx.x; i < n4_agg; i += stride)
        ((float4*)g_agg)[i] = z;
    for (size_t i = blockIdx.x * (size_t)blockDim.x + threadIdx.x; i < n4_deg; i += stride)
        ((float4*)g_deg)[i] = z;
}

// ---------------- kernel 3a: x scatter (L2 working set = x + agg_x ~ 102MB) ----
__global__ void edge_x_kernel(const void* __restrict__ ei_raw,
                              const float* __restrict__ x) {
    int warp = (blockIdx.x * blockDim.x + threadIdx.x) >> 5;
    int lane = threadIdx.x & 31;
    if (warp >= N_EDGES) return;

    int row = load_idx(ei_raw, warp);
    int col = load_idx(ei_raw, (size_t)N_EDGES + warp);
    if ((unsigned)row >= N_NODES || (unsigned)col >= N_NODES) return;

    float4 vx = ((const float4*)(x + (size_t)col * IN_CH))[lane];
    red_add_v4(g_agg + (size_t)row * AGG_W + lane * 4, vx);
    if (lane == 0) atomicAdd(&g_deg[row], 1.0f);
}

// ---------------- kernel 3b: tf scatter (streams tf, agg_t 26MB resident) ----
// half-warp per edge: lanes 0-15 -> edge 2w, lanes 16-31 -> edge 2w+1
__global__ void edge_t_kernel(const void* __restrict__ ei_raw,
                              const float* __restrict__ tf) {
    int warp = (blockIdx.x * blockDim.x + threadIdx.x) >> 5;
    int lane = threadIdx.x & 31;
    size_t edge = (size_t)warp * 2 + (lane >> 4);
    int l = lane & 15;
    if (edge >= N_EDGES) return;

    int row = load_idx(ei_raw, edge);
    if ((unsigned)row >= N_NODES) return;

    float4 vt = ((const float4*)tf)[edge * (T_DIM / 4) + l];
    red_add_v4(g_agg + (size_t)row * AGG_W + IN_CH + l * 4, vt);
}

// ---------------- kernel 4: node GEMM (FFMA2) + bias + relu ----------------
// C[100000][128] = relu( A[100000][320] @ g_Wt[320][128] + W_S_b + deg * g_cb )
#define BM 128
#define BN 128
#define BK 32
#define APAD 2   // keeps row stride 8B-aligned for LDS.64 and conflict-light

__global__ __launch_bounds__(256) void gemm_kernel(const float* __restrict__ x,
                                                   const float* __restrict__ Wsb,
                                                   float* __restrict__ out) {
    __shared__ float As[BK][BM + APAD];              // [k][m]
    __shared__ unsigned long long Bd[BK][BN];        // duplicated (b,b) pairs

    int m0 = blockIdx.x * BM;
    int tid = threadIdx.x;
    int tn = (tid & 31) * 4;     // n: 0..124
    int tm = (tid >> 5) * 16;    // m: 0..112 (warp-uniform)

    unsigned long long acc[8][4];   // [m-pair][n], each = (row 2p, row 2p+1)
#pragma unroll
    for (int p = 0; p < 8; p++)
#pragma unroll
        for (int j = 0; j < 4; j++) acc[p][j] = 0ull;

    for (int k0 = 0; k0 < 320; k0 += BK) {
        // ---- A tile: 128m x 32k, coalesced on k ----
#pragma unroll
        for (int i = 0; i < 16; i++) {
            int e = tid + i * 256;
            int m = e >> 5, k = e & 31;
            int node = m0 + m;
            int gk = k0 + k;
            float v = 0.f;
            if (node < N_NODES) {
                v = (gk < 128) ? x[(size_t)node * IN_CH + gk]
                               : g_agg[(size_t)node * AGG_W + (gk - 128)];
            }
            As[k][m] = v;
        }
        // ---- B tile: 32k x 128n, stored duplicated ----
#pragma unroll
        for (int i = 0; i < 4; i++) {
            int f = tid + i * 256;
            int k = f >> 5, n4 = f & 31;
            float4 w = ((const float4*)(g_Wt + (size_t)(k0 + k) * 128))[n4];
            Bd[k][n4 * 4 + 0] = pack2(w.x, w.x);
            Bd[k][n4 * 4 + 1] = pack2(w.y, w.y);
            Bd[k][n4 * 4 + 2] = pack2(w.z, w.z);
            Bd[k][n4 * 4 + 3] = pack2(w.w, w.w);
        }
        __syncthreads();

#pragma unroll
        for (int kk = 0; kk < BK; kk++) {
            ulonglong2 b01 = *((const ulonglong2*)&Bd[kk][tn]);
            ulonglong2 b23 = *((const ulonglong2*)&Bd[kk][tn + 2]);
#pragma unroll
            for (int p = 0; p < 8; p++) {
                // packed pair of adjacent m rows, free via LDS.64 (warp-broadcast)
                unsigned long long aa =
                    *((const unsigned long long*)&As[kk][tm + 2 * p]);
                fma2(acc[p][0], aa, b01.x);
                fma2(acc[p][1], aa, b01.y);
                fma2(acc[p][2], aa, b23.x);
                fma2(acc[p][3], aa, b23.y);
            }
        }
        __syncthreads();
    }

    // ---- epilogue ----
    float4 bsb = ((const float4*)Wsb)[tn >> 2];
    float4 cb4 = ((const float4*)g_cb)[tn >> 2];
#pragma unroll
    for (int p = 0; p < 8; p++) {
        float lo[4], hi[4];
#pragma unroll
        for (int j = 0; j < 4; j++) {
            float2 v = *((float2*)&acc[p][j]);
            lo[j] = v.x; hi[j] = v.y;
        }
        int node0 = m0 + tm + 2 * p;
#pragma unroll
        for (int r = 0; r < 2; r++) {
            int node = node0 + r;
            if (node < N_NODES) {
                float d = g_deg[node];
                const float* a = r ? hi : lo;
                float4 o;
                o.x = fmaxf(a[0] + bsb.x + d * cb4.x, 0.f);
                o.y = fmaxf(a[1] + bsb.y + d * cb4.y, 0.f);
                o.z = fmaxf(a[2] + bsb.z + d * cb4.z, 0.f);
                o.w = fmaxf(a[3] + bsb.w + d * cb4.w, 0.f);
                ((float4*)(out + (size_t)node * OUT_CH))[tn >> 2] = o;
            }
        }
    }
}

// ---------------- launcher ----------------
extern "C" void kernel_launch(void* const* d_in, const int* in_sizes, int n_in,
                              void* d_out, int out_size) {
    const float* x = nullptr; const void* ei = nullptr; const float* tf = nullptr;
    const float* Wsw = nullptr; const float* Wsb = nullptr;
    const float* Wtw = nullptr; const float* Wtb = nullptr;
    const float* Tw = nullptr;  const float* Tb = nullptr;
    int n16384 = 0, n128 = 0;
    for (int i = 0; i < n_in; i++) {
        long long s = in_sizes[i];
        void* p = d_in[i];
        if (s == (long long)N_NODES * IN_CH)      x  = (const float*)p;
        else if (s == 2LL * N_EDGES)              ei = (const void*)p;
        else if (s == (long long)N_EDGES * T_DIM) tf = (const float*)p;
        else if (s == OUT_CH * T_DIM)             Tw = (const float*)p;
        else if (s == OUT_CH * IN_CH) {
            if (n16384++ == 0) Wsw = (const float*)p; else Wtw = (const float*)p;
        } else if (s == OUT_CH) {
            if (n128 == 0) Wsb = (const float*)p;
            else if (n128 == 1) Wtb = (const float*)p;
            else Tb = (const float*)p;
            n128++;
        }
    }
    float* out = (float*)d_out;

    detect_kernel<<<1, 256>>>((const int*)ei);
    prep_kernel<<<(320 * 128 + 255) / 256, 256>>>(Wsw, Wtw, Tw, Wtb, Tb);
    zero_kernel<<<2048, 256>>>();
    edge_x_kernel<<<N_EDGES / 8, 256>>>(ei, x);          // 8 warps/block, 1 edge/warp
    edge_t_kernel<<<N_EDGES / 16, 256>>>(ei, tf);        // 2 edges/warp
    gemm_kernel<<<(N_NODES + BM - 1) / BM, 256>>>(x, Wsb, out);
}

// round 5
// speedup vs baseline: 1.6405x; 1.6405x over previous
#include <cuda_runtime.h>
#include <cuda_bf16.h>
#include <cstdint>

#define N_NODES 100000
#define N_EDGES 1000000
#define IN_CH   128
#define OUT_CH  128
#define T_DIM   64
#define AGG_W   192   // 128 (x-sum) + 64 (tf-sum)

// ---------------- device scratch ----------------
__device__ __align__(16) float g_agg[(size_t)N_NODES * AGG_W];
__device__ __align__(16) float g_deg[N_NODES];
__device__ __align__(16) float g_Wt[320 * 128];   // combined transposed weight [k][o]
__device__ __align__(16) float g_cb[128];         // W_T_b + T_b
__device__ int g_idx_is64;

// ---------------- helpers ----------------
__device__ __forceinline__ void red_add_v4(float* p, float4 v) {
    unsigned long long gp = __cvta_generic_to_global((void*)p);
    asm volatile("red.global.add.v4.f32 [%0], {%1,%2,%3,%4};"
                 :: "l"(gp), "f"(v.x), "f"(v.y), "f"(v.z), "f"(v.w)
                 : "memory");
}

// ---------------- kernel 0: detect edge_index dtype ----------------
__global__ void detect_kernel(const int* __restrict__ ei_raw) {
    __shared__ int any_nonzero;
    if (threadIdx.x == 0) any_nonzero = 0;
    __syncthreads();
    for (int i = threadIdx.x; i < 4096; i += blockDim.x)
        if (ei_raw[2 * i + 1] != 0) any_nonzero = 1;
    __syncthreads();
    if (threadIdx.x == 0) g_idx_is64 = (any_nonzero == 0);
}

__device__ __forceinline__ int load_idx(const void* ei_raw, size_t pos) {
    if (g_idx_is64) return (int)__ldg(&((const long long*)ei_raw)[pos]);
    return __ldg(&((const int*)ei_raw)[pos]);
}

// ---------------- kernel 1: build combined transposed weights ----------------
__global__ void prep_kernel(const float* __restrict__ Wsw,
                            const float* __restrict__ Wtw,
                            const float* __restrict__ Tw,
                            const float* __restrict__ Wtb,
                            const float* __restrict__ Tb) {
    int tid = blockIdx.x * blockDim.x + threadIdx.x;
    if (tid < 320 * 128) {
        int k = tid >> 7;
        int o = tid & 127;
        float v;
        if (k < 128)       v = Wsw[o * 128 + k];
        else if (k < 256)  v = Wtw[o * 128 + (k - 128)];
        else               v = Tw[o * 64 + (k - 256)];
        g_Wt[k * 128 + o] = v;
    }
    if (tid < 128) g_cb[tid] = Wtb[tid] + Tb[tid];
}

// ---------------- kernel 2: zero accumulators ----------------
__global__ void zero_kernel() {
    const size_t n4_agg = (size_t)N_NODES * AGG_W / 4;
    const size_t n4_deg = N_NODES / 4;
    float4 z = make_float4(0.f, 0.f, 0.f, 0.f);
    size_t stride = (size_t)gridDim.x * blockDim.x;
    for (size_t i = blockIdx.x * (size_t)blockDim.x + threadIdx.x; i < n4_agg; i += stride)
        ((float4*)g_agg)[i] = z;
    for (size_t i = blockIdx.x * (size_t)blockDim.x + threadIdx.x; i < n4_deg; i += stride)
        ((float4*)g_deg)[i] = z;
}

// ---------------- kernel 3a: x scatter, 4 edges per warp (MLP=4) ----------------
__global__ void edge_x_kernel(const void* __restrict__ ei_raw,
                              const float* __restrict__ x) {
    int warp = (blockIdx.x * blockDim.x + threadIdx.x) >> 5;
    int lane = threadIdx.x & 31;
    size_t e0 = (size_t)warp * 4;
    if (e0 >= N_EDGES) return;

    // lanes 0-3 load rows, lanes 4-7 load cols; broadcast via shfl
    int v = 0;
    if (lane < 4)      v = load_idx(ei_raw, e0 + lane);
    else if (lane < 8) v = load_idx(ei_raw, (size_t)N_EDGES + e0 + (lane - 4));

    int rows[4], cols[4];
#pragma unroll
    for (int i = 0; i < 4; i++) {
        rows[i] = __shfl_sync(0xffffffffu, v, i);
        cols[i] = __shfl_sync(0xffffffffu, v, 4 + i);
    }

    // issue all 4 independent gathers first (MLP), then the REDs
    float4 vx[4];
#pragma unroll
    for (int i = 0; i < 4; i++) {
        int c = ((unsigned)cols[i] < N_NODES) ? cols[i] : 0;
        vx[i] = __ldg(&((const float4*)(x + (size_t)c * IN_CH))[lane]);
    }
#pragma unroll
    for (int i = 0; i < 4; i++) {
        if ((unsigned)rows[i] >= N_NODES || (unsigned)cols[i] >= N_NODES) continue;
        red_add_v4(g_agg + (size_t)rows[i] * AGG_W + lane * 4, vx[i]);
    }
    if (lane < 4 && (unsigned)rows[lane] < N_NODES)
        atomicAdd(&g_deg[rows[lane]], 1.0f);
}

// ---------------- kernel 3b: tf scatter (streams tf), 2 edges per warp ----------
__global__ void edge_t_kernel(const void* __restrict__ ei_raw,
                              const float* __restrict__ tf) {
    int warp = (blockIdx.x * blockDim.x + threadIdx.x) >> 5;
    int lane = threadIdx.x & 31;
    size_t edge = (size_t)warp * 2 + (lane >> 4);
    int l = lane & 15;
    if (edge >= N_EDGES) return;

    int row = load_idx(ei_raw, edge);
    float4 vt = __ldg(&((const float4*)tf)[edge * (T_DIM / 4) + l]);
    if ((unsigned)row >= N_NODES) return;
    red_add_v4(g_agg + (size_t)row * AGG_W + IN_CH + l * 4, vt);
}

// ---------------- kernel 4: node GEMM + bias + relu (scalar, proven) ----------
// C[100000][128] = relu( A[100000][320] @ g_Wt[320][128] + W_S_b + deg * g_cb )
#define BM 64
#define BN 128
#define BK 32

__global__ __launch_bounds__(256) void gemm_kernel(const float* __restrict__ x,
                                                   const float* __restrict__ Wsb,
                                                   float* __restrict__ out) {
    __shared__ float As[BK][BM + 1];
    __shared__ float Bs[BK][BN];

    int m0 = blockIdx.x * BM;
    int tid = threadIdx.x;
    int tn = (tid & 31) * 4;    // n: 0..124
    int tm = (tid >> 5) * 8;    // m: 0..56 (warp-uniform -> LDS broadcast)

    float acc[8][4];
#pragma unroll
    for (int i = 0; i < 8; i++)
#pragma unroll
        for (int j = 0; j < 4; j++) acc[i][j] = 0.f;

    for (int k0 = 0; k0 < 320; k0 += BK) {
#pragma unroll
        for (int i = 0; i < 8; i++) {
            int e = tid + i * 256;
            int m = e >> 5, k = e & 31;
            int node = m0 + m;
            float v = 0.f;
            int gk = k0 + k;
            if (node < N_NODES) {
                v = (gk < 128) ? x[(size_t)node * IN_CH + gk]
                               : g_agg[(size_t)node * AGG_W + (gk - 128)];
            }
            As[k][m] = v;
        }
#pragma unroll
        for (int i = 0; i < 4; i++) {
            int f = tid + i * 256;
            int k = f >> 5, n4 = f & 31;
            float4 w = ((const float4*)(g_Wt + (size_t)(k0 + k) * 128))[n4];
            *((float4*)&Bs[k][n4 * 4]) = w;
        }
        __syncthreads();

#pragma unroll
        for (int kk = 0; kk < BK; kk++) {
            float4 bb = *((const float4*)&Bs[kk][tn]);
#pragma unroll
            for (int i = 0; i < 8; i++) {
                float a = As[kk][tm + i];
                acc[i][0] += a * bb.x;
                acc[i][1] += a * bb.y;
                acc[i][2] += a * bb.z;
                acc[i][3] += a * bb.w;
            }
        }
        __syncthreads();
    }

    float4 bsb = ((const float4*)Wsb)[tn >> 2];
    float4 cb4 = ((const float4*)g_cb)[tn >> 2];
#pragma unroll
    for (int i = 0; i < 8; i++) {
        int node = m0 + tm + i;
        if (node < N_NODES) {
            float d = g_deg[node];
            float4 o;
            o.x = fmaxf(acc[i][0] + bsb.x + d * cb4.x, 0.f);
            o.y = fmaxf(acc[i][1] + bsb.y + d * cb4.y, 0.f);
            o.z = fmaxf(acc[i][2] + bsb.z + d * cb4.z, 0.f);
            o.w = fmaxf(acc[i][3] + bsb.w + d * cb4.w, 0.f);
            ((float4*)(out + (size_t)node * OUT_CH))[tn >> 2] = o;
        }
    }
}

// ---------------- launcher ----------------
extern "C" void kernel_launch(void* const* d_in, const int* in_sizes, int n_in,
                              void* d_out, int out_size) {
    const float* x = nullptr; const void* ei = nullptr; const float* tf = nullptr;
    const float* Wsw = nullptr; const float* Wsb = nullptr;
    const float* Wtw = nullptr; const float* Wtb = nullptr;
    const float* Tw = nullptr;  const float* Tb = nullptr;
    int n16384 = 0, n128 = 0;
    for (int i = 0; i < n_in; i++) {
        long long s = in_sizes[i];
        void* p = d_in[i];
        if (s == (long long)N_NODES * IN_CH)      x  = (const float*)p;
        else if (s == 2LL * N_EDGES)              ei = (const void*)p;
        else if (s == (long long)N_EDGES * T_DIM) tf = (const float*)p;
        else if (s == OUT_CH * T_DIM)             Tw = (const float*)p;
        else if (s == OUT_CH * IN_CH) {
            if (n16384++ == 0) Wsw = (const float*)p; else Wtw = (const float*)p;
        } else if (s == OUT_CH) {
            if (n128 == 0) Wsb = (const float*)p;
            else if (n128 == 1) Wtb = (const float*)p;
            else Tb = (const float*)p;
            n128++;
        }
    }
    float* out = (float*)d_out;

    detect_kernel<<<1, 256>>>((const int*)ei);
    prep_kernel<<<(320 * 128 + 255) / 256, 256>>>(Wsw, Wtw, Tw, Wtb, Tb);
    zero_kernel<<<2048, 256>>>();
    edge_x_kernel<<<(N_EDGES / 4) / 8, 256>>>(ei, x);    // 4 edges/warp, 8 warps/block
    edge_t_kernel<<<N_EDGES / 16, 256>>>(ei, tf);        // 2 edges/warp
    gemm_kernel<<<(N_NODES + BM - 1) / BM, 256>>>(x, Wsb, out);
}

// round 7
// speedup vs baseline: 2.8458x; 1.7347x over previous
#include <cuda_runtime.h>
#include <cuda_bf16.h>
#include <cstdint>

#define N_NODES 100000
#define N_EDGES 1000000
#define IN_CH   128
#define OUT_CH  128
#define T_DIM   64
#define AGG_W   192

// ---------------- device scratch ----------------
__device__ __align__(16) float g_agg[(size_t)N_NODES * AGG_W];
__device__ __align__(16) float g_deg[N_NODES];
__device__ __align__(16) float g_cb[128];         // W_T_b + T_b
__device__ int g_idx_is64;

// ---------------- generic helpers ----------------
__device__ __forceinline__ void red_add_v4(float* p, float4 v) {
    unsigned long long gp = __cvta_generic_to_global((void*)p);
    asm volatile("red.global.add.v4.f32 [%0], {%1,%2,%3,%4};"
                 :: "l"(gp), "f"(v.x), "f"(v.y), "f"(v.z), "f"(v.w)
                 : "memory");
}
__device__ __forceinline__ uint32_t smem_u32(const void* p) {
    uint32_t a;
    asm("{ .reg .u64 t; cvta.to.shared.u64 t, %1; cvt.u32.u64 %0, t; }"
        : "=r"(a) : "l"(p));
    return a;
}
#define SW128(o) ((o) ^ (((o) >> 3) & 0x70))

__device__ __forceinline__ void ldmx4(uint32_t addr, uint32_t& r0, uint32_t& r1,
                                      uint32_t& r2, uint32_t& r3) {
    asm volatile("ldmatrix.sync.aligned.m8n8.x4.shared.b16 {%0,%1,%2,%3}, [%4];"
                 : "=r"(r0), "=r"(r1), "=r"(r2), "=r"(r3) : "r"(addr));
}
__device__ __forceinline__ void mma_bf16(float* c, const uint32_t* a, const uint32_t* b) {
    asm volatile("mma.sync.aligned.m16n8k16.row.col.f32.bf16.bf16.f32 "
                 "{%0,%1,%2,%3}, {%4,%5,%6,%7}, {%8,%9}, {%0,%1,%2,%3};"
                 : "+f"(c[0]), "+f"(c[1]), "+f"(c[2]), "+f"(c[3])
                 : "r"(a[0]), "r"(a[1]), "r"(a[2]), "r"(a[3]), "r"(b[0]), "r"(b[1]));
}

// ---------------- kernel 0: detect edge_index dtype ----------------
__global__ void detect_kernel(const int* __restrict__ ei_raw) {
    __shared__ int any_nonzero;
    if (threadIdx.x == 0) any_nonzero = 0;
    __syncthreads();
    for (int i = threadIdx.x; i < 4096; i += blockDim.x)
        if (ei_raw[2 * i + 1] != 0) any_nonzero = 1;
    __syncthreads();
    if (threadIdx.x == 0) g_idx_is64 = (any_nonzero == 0);
}
__device__ __forceinline__ int load_idx(const void* ei_raw, size_t pos) {
    if (g_idx_is64) return (int)__ldg(&((const long long*)ei_raw)[pos]);
    return __ldg(&((const int*)ei_raw)[pos]);
}

// ---------------- kernel 1: combined bias ----------------
__global__ void prep_kernel(const float* __restrict__ Wtb, const float* __restrict__ Tb) {
    int tid = threadIdx.x;
    if (tid < 128) g_cb[tid] = Wtb[tid] + Tb[tid];
}

// ---------------- kernel 2: zero accumulators ----------------
__global__ void zero_kernel() {
    const size_t n4_agg = (size_t)N_NODES * AGG_W / 4;
    const size_t n4_deg = N_NODES / 4;
    float4 z = make_float4(0.f, 0.f, 0.f, 0.f);
    size_t stride = (size_t)gridDim.x * blockDim.x;
    for (size_t i = blockIdx.x * (size_t)blockDim.x + threadIdx.x; i < n4_agg; i += stride)
        ((float4*)g_agg)[i] = z;
    for (size_t i = blockIdx.x * (size_t)blockDim.x + threadIdx.x; i < n4_deg; i += stride)
        ((float4*)g_deg)[i] = z;
}

// ---------------- kernel 3a: x scatter, 4 edges/warp ----------------
__global__ void edge_x_kernel(const void* __restrict__ ei_raw,
                              const float* __restrict__ x) {
    int warp = (blockIdx.x * blockDim.x + threadIdx.x) >> 5;
    int lane = threadIdx.x & 31;
    size_t e0 = (size_t)warp * 4;
    if (e0 >= N_EDGES) return;

    int v = 0;
    if (lane < 4)      v = load_idx(ei_raw, e0 + lane);
    else if (lane < 8) v = load_idx(ei_raw, (size_t)N_EDGES + e0 + (lane - 4));

    int rows[4], cols[4];
#pragma unroll
    for (int i = 0; i < 4; i++) {
        rows[i] = __shfl_sync(0xffffffffu, v, i);
        cols[i] = __shfl_sync(0xffffffffu, v, 4 + i);
    }
    float4 vx[4];
#pragma unroll
    for (int i = 0; i < 4; i++) {
        int c = ((unsigned)cols[i] < N_NODES) ? cols[i] : 0;
        vx[i] = __ldg(&((const float4*)(x + (size_t)c * IN_CH))[lane]);
    }
#pragma unroll
    for (int i = 0; i < 4; i++) {
        if ((unsigned)rows[i] >= N_NODES || (unsigned)cols[i] >= N_NODES) continue;
        red_add_v4(g_agg + (size_t)rows[i] * AGG_W + lane * 4, vx[i]);
    }
    if (lane < 4 && (unsigned)rows[lane] < N_NODES)
        atomicAdd(&g_deg[rows[lane]], 1.0f);
}

// ---------------- kernel 3b: tf scatter, 2 edges/warp ----------------
__global__ void edge_t_kernel(const void* __restrict__ ei_raw,
                              const float* __restrict__ tf) {
    int warp = (blockIdx.x * blockDim.x + threadIdx.x) >> 5;
    int lane = threadIdx.x & 31;
    size_t edge = (size_t)warp * 2 + (lane >> 4);
    int l = lane & 15;
    if (edge >= N_EDGES) return;

    int row = load_idx(ei_raw, edge);
    float4 vt = __ldg(&((const float4*)tf)[edge * (T_DIM / 4) + l]);
    if ((unsigned)row >= N_NODES) return;
    red_add_v4(g_agg + (size_t)row * AGG_W + IN_CH + l * 4, vt);
}

// ---------------- kernel 4: mma.sync GEMM (bf16 3-term split) ----------------
// C[100000][128] = relu( A[100000][320] @ B^T + Wsb + deg * cb )
// A row = [x | agg_x | agg_t]; B rows (n,k) = [Wsw | Wtw | Tw] (already K-major)
#define KCH 64
#define NCHUNK 5
#define SO_AHI 0
#define SO_ALO 16384
#define SO_BHI 32768
#define SO_BLO 49152
#define SMEM_SZ 65536

__device__ __forceinline__ void cvt_split2(float a, float b, uint32_t& h, uint32_t& l) {
    __nv_bfloat162 hb = __floats2bfloat162_rn(a, b);
    float2 hf = __bfloat1622float2(hb);
    __nv_bfloat162 lb = __floats2bfloat162_rn(a - hf.x, b - hf.y);
    h = *(uint32_t*)&hb;
    l = *(uint32_t*)&lb;
}

__global__ void __launch_bounds__(256, 1)
gemm_mma_kernel(const float* __restrict__ x,
                const float* __restrict__ Wsw, const float* __restrict__ Wtw,
                const float* __restrict__ Tw,  const float* __restrict__ Wsb,
                float* __restrict__ out) {
    extern __shared__ char smem[];
    const uint32_t sb = smem_u32(smem);
    const int tid = threadIdx.x;
    const int wid = tid >> 5;
    const int lane = tid & 31;
    const int m0 = blockIdx.x * 128;
    const int wm = (wid >> 2) * 64;   // warp m offset in block: 0 or 64
    const int wn = (wid & 3) * 32;    // warp n offset: 0,32,64,96
    const int g = lane >> 2;          // group id 0..7
    const int t = lane & 3;           // thread-in-group

    float acc[4][4][4];               // [m-tile][n-tile][4 c-regs]
#pragma unroll
    for (int i = 0; i < 4; i++)
#pragma unroll
        for (int j = 0; j < 4; j++)
#pragma unroll
            for (int r = 0; r < 4; r++) acc[i][j][r] = 0.f;

    for (int c = 0; c < NCHUNK; c++) {
        int gk0 = c * KCH;
        // ---- load + convert A chunk: 128 rows x 64 k ----
#pragma unroll
        for (int it = 0; it < 4; it++) {
            int task = tid + it * 256;
            int m = task >> 3, gg = task & 7;
            int node = m0 + m;
            int gk = gk0 + gg * 8;
            float4 v0 = make_float4(0, 0, 0, 0), v1 = v0;
            if (node < N_NODES) {
                const float* base = (gk < 128)
                    ? (x + (size_t)node * IN_CH + gk)
                    : (g_agg + (size_t)node * AGG_W + (gk - 128));
                v0 = __ldg((const float4*)base);
                v1 = __ldg((const float4*)(base + 4));
            }
            uint4 H, L;
            cvt_split2(v0.x, v0.y, H.x, L.x);
            cvt_split2(v0.z, v0.w, H.y, L.y);
            cvt_split2(v1.x, v1.y, H.z, L.z);
            cvt_split2(v1.z, v1.w, H.w, L.w);
            uint32_t off = SW128((uint32_t)(m * 128 + gg * 16));
            *(uint4*)(smem + SO_AHI + off) = H;
            *(uint4*)(smem + SO_ALO + off) = L;
        }
        // ---- load + convert B chunk: 128 n-rows x 64 k ----
        const float* bbase; int bstride;
        if (c < 2)      { bbase = Wsw + c * 64;       bstride = 128; }
        else if (c < 4) { bbase = Wtw + (c - 2) * 64; bstride = 128; }
        else            { bbase = Tw;                 bstride = 64;  }
#pragma unroll
        for (int it = 0; it < 4; it++) {
            int task = tid + it * 256;
            int n = task >> 3, gg = task & 7;
            const float* p = bbase + (size_t)n * bstride + gg * 8;
            float4 v0 = __ldg((const float4*)p);
            float4 v1 = __ldg((const float4*)(p + 4));
            uint4 H, L;
            cvt_split2(v0.x, v0.y, H.x, L.x);
            cvt_split2(v0.z, v0.w, H.y, L.y);
            cvt_split2(v1.x, v1.y, H.z, L.z);
            cvt_split2(v1.z, v1.w, H.w, L.w);
            uint32_t off = SW128((uint32_t)(n * 128 + gg * 16));
            *(uint4*)(smem + SO_BHI + off) = H;
            *(uint4*)(smem + SO_BLO + off) = L;
        }
        __syncthreads();

        // ---- compute: 4 k16-steps per chunk ----
#pragma unroll
        for (int ks = 0; ks < 4; ks++) {
            int kk = ks * 16;   // k offset within chunk (elements)

            // A fragment addresses (per lane): 4 submatrix rows pattern
            // lanes 0-7: (mrow+l, kk) | 8-15: (mrow+8+l', kk) | 16-23: (mrow+l'', kk+8) | 24-31: (+8, kk+8)
            uint32_t a_hi[4][4], a_lo[4][4];
#pragma unroll
            for (int mi = 0; mi < 4; mi++) {
                int mrow = wm + mi * 16;
                int r = mrow + (lane & 7) + ((lane & 8) ? 8 : 0);
                int kb = (kk + ((lane & 16) ? 8 : 0)) * 2;
                uint32_t off = SW128((uint32_t)(r * 128 + kb));
                ldmx4(sb + SO_AHI + off, a_hi[mi][0], a_hi[mi][1], a_hi[mi][2], a_hi[mi][3]);
                ldmx4(sb + SO_ALO + off, a_lo[mi][0], a_lo[mi][1], a_lo[mi][2], a_lo[mi][3]);
            }
            // B fragments: 2 ldmatrix.x4 cover 4 n8-tiles (hi), same for lo
            // lanes 0-7: (n0+l, kk) | 8-15: (n0+l', kk+8) | 16-23: (n0+8+l'', kk) | 24-31: (n0+8+l''', kk+8)
            uint32_t b_hi[4][2], b_lo[4][2];
#pragma unroll
            for (int nh = 0; nh < 2; nh++) {
                int n0 = wn + nh * 16;
                int r = n0 + (lane & 7) + ((lane & 16) ? 8 : 0);
                int kb = (kk + ((lane & 8) ? 8 : 0)) * 2;
                uint32_t off = SW128((uint32_t)(r * 128 + kb));
                uint32_t q0, q1, q2, q3;
                ldmx4(sb + SO_BHI + off, q0, q1, q2, q3);
                b_hi[nh * 2][0] = q0; b_hi[nh * 2][1] = q1;
                b_hi[nh * 2 + 1][0] = q2; b_hi[nh * 2 + 1][1] = q3;
                ldmx4(sb + SO_BLO + off, q0, q1, q2, q3);
                b_lo[nh * 2][0] = q0; b_lo[nh * 2][1] = q1;
                b_lo[nh * 2 + 1][0] = q2; b_lo[nh * 2 + 1][1] = q3;
            }
#pragma unroll
            for (int mi = 0; mi < 4; mi++)
#pragma unroll
                for (int ni = 0; ni < 4; ni++) {
                    mma_bf16(acc[mi][ni], a_hi[mi], b_hi[ni]);
                    mma_bf16(acc[mi][ni], a_lo[mi], b_hi[ni]);
                    mma_bf16(acc[mi][ni], a_hi[mi], b_lo[ni]);
                }
        }
        __syncthreads();
    }

    // ---- epilogue: bias + deg*cb + relu, store ----
#pragma unroll
    for (int mi = 0; mi < 4; mi++) {
        int row0 = m0 + wm + mi * 16 + g;
        int row1 = row0 + 8;
        float d0 = (row0 < N_NODES) ? g_deg[row0] : 0.f;
        float d1 = (row1 < N_NODES) ? g_deg[row1] : 0.f;
#pragma unroll
        for (int ni = 0; ni < 4; ni++) {
            int cn = wn + ni * 8 + t * 2;
            float2 bs = *(const float2*)(Wsb + cn);
            float2 cb = *(const float2*)(g_cb + cn);
            if (row0 < N_NODES) {
                float2 o;
                o.x = fmaxf(acc[mi][ni][0] + bs.x + d0 * cb.x, 0.f);
                o.y = fmaxf(acc[mi][ni][1] + bs.y + d0 * cb.y, 0.f);
                *(float2*)(out + (size_t)row0 * OUT_CH + cn) = o;
            }
            if (row1 < N_NODES) {
                float2 o;
                o.x = fmaxf(acc[mi][ni][2] + bs.x + d1 * cb.x, 0.f);
                o.y = fmaxf(acc[mi][ni][3] + bs.y + d1 * cb.y, 0.f);
                *(float2*)(out + (size_t)row1 * OUT_CH + cn) = o;
            }
        }
    }
}

// ---------------- launcher ----------------
extern "C" void kernel_launch(void* const* d_in, const int* in_sizes, int n_in,
                              void* d_out, int out_size) {
    const float* x = nullptr; const void* ei = nullptr; const float* tf = nullptr;
    const float* Wsw = nullptr; const float* Wsb = nullptr;
    const float* Wtw = nullptr; const float* Wtb = nullptr;
    const float* Tw = nullptr;  const float* Tb = nullptr;
    int n16384 = 0, n128 = 0;
    for (int i = 0; i < n_in; i++) {
        long long s = in_sizes[i];
        void* p = d_in[i];
        if (s == (long long)N_NODES * IN_CH)      x  = (const float*)p;
        else if (s == 2LL * N_EDGES)              ei = (const void*)p;
        else if (s == (long long)N_EDGES * T_DIM) tf = (const float*)p;
        else if (s == OUT_CH * T_DIM)             Tw = (const float*)p;
        else if (s == OUT_CH * IN_CH) {
            if (n16384++ == 0) Wsw = (const float*)p; else Wtw = (const float*)p;
        } else if (s == OUT_CH) {
            if (n128 == 0) Wsb = (const float*)p;
            else if (n128 == 1) Wtb = (const float*)p;
            else Tb = (const float*)p;
            n128++;
        }
    }
    float* out = (float*)d_out;

    cudaFuncSetAttribute(gemm_mma_kernel,
                         cudaFuncAttributeMaxDynamicSharedMemorySize, SMEM_SZ);

    detect_kernel<<<1, 256>>>((const int*)ei);
    prep_kernel<<<1, 128>>>(Wtb, Tb);
    zero_kernel<<<2048, 256>>>();
    edge_x_kernel<<<(N_EDGES / 4) / 8, 256>>>(ei, x);
    edge_t_kernel<<<N_EDGES / 16, 256>>>(ei, tf);
    gemm_mma_kernel<<<(N_NODES + 127) / 128, 256, SMEM_SZ>>>(x, Wsw, Wtw, Tw, Wsb, out);
}

// round 8
// speedup vs baseline: 3.3836x; 1.1890x over previous
#include <cuda_runtime.h>
#include <cuda_bf16.h>
#include <cstdint>

#define N_NODES 100000
#define N_EDGES 1000000
#define IN_CH   128
#define OUT_CH  128
#define T_DIM   64
#define AGG_W   192

// ---------------- device scratch ----------------
__device__ __align__(16) float g_agg[(size_t)N_NODES * AGG_W];
__device__ __align__(16) float g_deg[N_NODES];
__device__ __align__(16) float g_cb[128];         // W_T_b + T_b
__device__ int g_idx_is64;

// ---------------- generic helpers ----------------
__device__ __forceinline__ void red_add_v4(float* p, float4 v) {
    unsigned long long gp = __cvta_generic_to_global((void*)p);
    asm volatile("red.global.add.v4.f32 [%0], {%1,%2,%3,%4};"
                 :: "l"(gp), "f"(v.x), "f"(v.y), "f"(v.z), "f"(v.w)
                 : "memory");
}
__device__ __forceinline__ uint32_t smem_u32(const void* p) {
    uint32_t a;
    asm("{ .reg .u64 t; cvta.to.shared.u64 t, %1; cvt.u32.u64 %0, t; }"
        : "=r"(a) : "l"(p));
    return a;
}
#define SW128(o) ((o) ^ (((o) >> 3) & 0x70))

__device__ __forceinline__ void ldmx4(uint32_t addr, uint32_t& r0, uint32_t& r1,
                                      uint32_t& r2, uint32_t& r3) {
    asm volatile("ldmatrix.sync.aligned.m8n8.x4.shared.b16 {%0,%1,%2,%3}, [%4];"
                 : "=r"(r0), "=r"(r1), "=r"(r2), "=r"(r3) : "r"(addr));
}
__device__ __forceinline__ void mma_bf16(float* c, const uint32_t* a, const uint32_t* b) {
    asm volatile("mma.sync.aligned.m16n8k16.row.col.f32.bf16.bf16.f32 "
                 "{%0,%1,%2,%3}, {%4,%5,%6,%7}, {%8,%9}, {%0,%1,%2,%3};"
                 : "+f"(c[0]), "+f"(c[1]), "+f"(c[2]), "+f"(c[3])
                 : "r"(a[0]), "r"(a[1]), "r"(a[2]), "r"(a[3]), "r"(b[0]), "r"(b[1]));
}

// ---------------- kernel 0: detect edge_index dtype ----------------
__global__ void detect_kernel(const int* __restrict__ ei_raw) {
    __shared__ int any_nonzero;
    if (threadIdx.x == 0) any_nonzero = 0;
    __syncthreads();
    for (int i = threadIdx.x; i < 4096; i += blockDim.x)
        if (ei_raw[2 * i + 1] != 0) any_nonzero = 1;
    __syncthreads();
    if (threadIdx.x == 0) g_idx_is64 = (any_nonzero == 0);
}
__device__ __forceinline__ int load_idx(const void* ei_raw, size_t pos) {
    if (g_idx_is64) return (int)__ldg(&((const long long*)ei_raw)[pos]);
    return __ldg(&((const int*)ei_raw)[pos]);
}

// ---------------- kernel 1: combined bias ----------------
__global__ void prep_kernel(const float* __restrict__ Wtb, const float* __restrict__ Tb) {
    int tid = threadIdx.x;
    if (tid < 128) g_cb[tid] = Wtb[tid] + Tb[tid];
}

// ---------------- kernel 2: zero accumulators ----------------
__global__ void zero_kernel() {
    const size_t n4_agg = (size_t)N_NODES * AGG_W / 4;
    const size_t n4_deg = N_NODES / 4;
    float4 z = make_float4(0.f, 0.f, 0.f, 0.f);
    size_t stride = (size_t)gridDim.x * blockDim.x;
    for (size_t i = blockIdx.x * (size_t)blockDim.x + threadIdx.x; i < n4_agg; i += stride)
        ((float4*)g_agg)[i] = z;
    for (size_t i = blockIdx.x * (size_t)blockDim.x + threadIdx.x; i < n4_deg; i += stride)
        ((float4*)g_deg)[i] = z;
}

// ---------------- kernel 3a: x scatter, 8 edges/warp (MLP=8) ----------------
__global__ void edge_x_kernel(const void* __restrict__ ei_raw,
                              const float* __restrict__ x) {
    int warp = (blockIdx.x * blockDim.x + threadIdx.x) >> 5;
    int lane = threadIdx.x & 31;
    size_t e0 = (size_t)warp * 8;
    if (e0 >= N_EDGES) return;

    int v = 0;
    if (lane < 8)       v = load_idx(ei_raw, e0 + lane);
    else if (lane < 16) v = load_idx(ei_raw, (size_t)N_EDGES + e0 + (lane - 8));

    int rows[8], cols[8];
#pragma unroll
    for (int i = 0; i < 8; i++) {
        rows[i] = __shfl_sync(0xffffffffu, v, i);
        cols[i] = __shfl_sync(0xffffffffu, v, 8 + i);
    }
    float4 vx[8];
#pragma unroll
    for (int i = 0; i < 8; i++) {
        int c = ((unsigned)cols[i] < N_NODES) ? cols[i] : 0;
        vx[i] = __ldg(&((const float4*)(x + (size_t)c * IN_CH))[lane]);
    }
#pragma unroll
    for (int i = 0; i < 8; i++) {
        if ((unsigned)rows[i] >= N_NODES || (unsigned)cols[i] >= N_NODES) continue;
        red_add_v4(g_agg + (size_t)rows[i] * AGG_W + lane * 4, vx[i]);
    }
    if (lane < 8 && (unsigned)rows[lane] < N_NODES)
        atomicAdd(&g_deg[rows[lane]], 1.0f);
}

// ---------------- kernel 3b: tf scatter, 8 edges/warp (MLP=4) ----------------
// half-warp owns one edge per pass; 4 passes, all loads issued first
__global__ void edge_t_kernel(const void* __restrict__ ei_raw,
                              const float* __restrict__ tf) {
    int warp = (blockIdx.x * blockDim.x + threadIdx.x) >> 5;
    int lane = threadIdx.x & 31;
    size_t e0 = (size_t)warp * 8;
    if (e0 >= N_EDGES) return;
    int half = lane >> 4;      // 0/1
    int l = lane & 15;

    int v = 0;
    if (lane < 8) v = load_idx(ei_raw, e0 + lane);
    int rows[4];
    size_t edges[4];
#pragma unroll
    for (int p = 0; p < 4; p++) {
        edges[p] = e0 + 2 * p + half;
        rows[p] = __shfl_sync(0xffffffffu, v, 2 * p + half);
    }
    float4 vt[4];
#pragma unroll
    for (int p = 0; p < 4; p++)
        vt[p] = __ldg(&((const float4*)tf)[edges[p] * (T_DIM / 4) + l]);
#pragma unroll
    for (int p = 0; p < 4; p++) {
        if ((unsigned)rows[p] >= N_NODES) continue;
        red_add_v4(g_agg + (size_t)rows[p] * AGG_W + IN_CH + l * 4, vt[p]);
    }
}

// ---------------- kernel 4: mma.sync GEMM (bf16 3-term split, 2-stage) --------
// C[100000][128] = relu( A[100000][320] @ B^T + Wsb + deg * cb )
#define KCH 64
#define NCHUNK 5
#define BUF_SZ 65536          // AHI|ALO|BHI|BLO, 16KB each
#define SMEM_SZ (2 * BUF_SZ)  // double buffered

__device__ __forceinline__ void cvt_split2(float a, float b, uint32_t& h, uint32_t& l) {
    __nv_bfloat162 hb = __floats2bfloat162_rn(a, b);
    float2 hf = __bfloat1622float2(hb);
    __nv_bfloat162 lb = __floats2bfloat162_rn(a - hf.x, b - hf.y);
    h = *(uint32_t*)&hb;
    l = *(uint32_t*)&lb;
}

struct Stage { float4 a[8]; float4 b[8]; };  // per-thread staged chunk (64+64 floats)

__device__ __forceinline__ void load_chunk(Stage& s, int c, int m0, int tid,
                                           const float* __restrict__ x,
                                           const float* __restrict__ Wsw,
                                           const float* __restrict__ Wtw,
                                           const float* __restrict__ Tw) {
    int gk0 = c * KCH;
#pragma unroll
    for (int it = 0; it < 4; it++) {
        int task = tid + it * 256;
        int m = task >> 3, gg = task & 7;
        int node = m0 + m;
        int gk = gk0 + gg * 8;
        float4 v0 = make_float4(0, 0, 0, 0), v1 = v0;
        if (node < N_NODES) {
            const float* base = (gk < 128)
                ? (x + (size_t)node * IN_CH + gk)
                : (g_agg + (size_t)node * AGG_W + (gk - 128));
            v0 = __ldg((const float4*)base);
            v1 = __ldg((const float4*)(base + 4));
        }
        s.a[it * 2] = v0; s.a[it * 2 + 1] = v1;
    }
    const float* bbase; int bstride;
    if (c < 2)      { bbase = Wsw + c * 64;       bstride = 128; }
    else if (c < 4) { bbase = Wtw + (c - 2) * 64; bstride = 128; }
    else            { bbase = Tw;                 bstride = 64;  }
#pragma unroll
    for (int it = 0; it < 4; it++) {
        int task = tid + it * 256;
        int n = task >> 3, gg = task & 7;
        const float* p = bbase + (size_t)n * bstride + gg * 8;
        s.b[it * 2]     = __ldg((const float4*)p);
        s.b[it * 2 + 1] = __ldg((const float4*)(p + 4));
    }
}

__device__ __forceinline__ void store_chunk(const Stage& s, char* buf, int tid) {
#pragma unroll
    for (int it = 0; it < 4; it++) {
        int task = tid + it * 256;
        int m = task >> 3, gg = task & 7;
        uint32_t off = SW128((uint32_t)(m * 128 + gg * 16));
        float4 v0 = s.a[it * 2], v1 = s.a[it * 2 + 1];
        uint4 H, L;
        cvt_split2(v0.x, v0.y, H.x, L.x);
        cvt_split2(v0.z, v0.w, H.y, L.y);
        cvt_split2(v1.x, v1.y, H.z, L.z);
        cvt_split2(v1.z, v1.w, H.w, L.w);
        *(uint4*)(buf + off) = H;              // AHI
        *(uint4*)(buf + 16384 + off) = L;      // ALO
        v0 = s.b[it * 2]; v1 = s.b[it * 2 + 1];
        cvt_split2(v0.x, v0.y, H.x, L.x);
        cvt_split2(v0.z, v0.w, H.y, L.y);
        cvt_split2(v1.x, v1.y, H.z, L.z);
        cvt_split2(v1.z, v1.w, H.w, L.w);
        *(uint4*)(buf + 32768 + off) = H;      // BHI
        *(uint4*)(buf + 49152 + off) = L;      // BLO
    }
}

__global__ void __launch_bounds__(256, 1)
gemm_mma_kernel(const float* __restrict__ x,
                const float* __restrict__ Wsw, const float* __restrict__ Wtw,
                const float* __restrict__ Tw,  const float* __restrict__ Wsb,
                float* __restrict__ out) {
    extern __shared__ char smem[];
    const uint32_t sb = smem_u32(smem);
    const int tid = threadIdx.x;
    const int wid = tid >> 5;
    const int lane = tid & 31;
    const int m0 = blockIdx.x * 128;
    const int wm = (wid >> 2) * 64;
    const int wn = (wid & 3) * 32;
    const int g = lane >> 2;
    const int t = lane & 3;

    float acc[4][4][4];
#pragma unroll
    for (int i = 0; i < 4; i++)
#pragma unroll
        for (int j = 0; j < 4; j++)
#pragma unroll
            for (int r = 0; r < 4; r++) acc[i][j][r] = 0.f;

    Stage st;
    load_chunk(st, 0, m0, tid, x, Wsw, Wtw, Tw);
    store_chunk(st, smem, tid);
    __syncthreads();

    for (int c = 0; c < NCHUNK; c++) {
        if (c + 1 < NCHUNK)
            load_chunk(st, c + 1, m0, tid, x, Wsw, Wtw, Tw);  // LDGs fly over MMAs

        uint32_t base = sb + (c & 1) * BUF_SZ;
#pragma unroll
        for (int ks = 0; ks < 4; ks++) {
            int kk = ks * 16;
            uint32_t a_hi[4][4], a_lo[4][4];
#pragma unroll
            for (int mi = 0; mi < 4; mi++) {
                int mrow = wm + mi * 16;
                int r = mrow + (lane & 7) + ((lane & 8) ? 8 : 0);
                int kb = (kk + ((lane & 16) ? 8 : 0)) * 2;
                uint32_t off = SW128((uint32_t)(r * 128 + kb));
                ldmx4(base + off, a_hi[mi][0], a_hi[mi][1], a_hi[mi][2], a_hi[mi][3]);
                ldmx4(base + 16384 + off, a_lo[mi][0], a_lo[mi][1], a_lo[mi][2], a_lo[mi][3]);
            }
            uint32_t b_hi[4][2], b_lo[4][2];
#pragma unroll
            for (int nh = 0; nh < 2; nh++) {
                int n0 = wn + nh * 16;
                int r = n0 + (lane & 7) + ((lane & 16) ? 8 : 0);
                int kb = (kk + ((lane & 8) ? 8 : 0)) * 2;
                uint32_t off = SW128((uint32_t)(r * 128 + kb));
                uint32_t q0, q1, q2, q3;
                ldmx4(base + 32768 + off, q0, q1, q2, q3);
                b_hi[nh * 2][0] = q0; b_hi[nh * 2][1] = q1;
                b_hi[nh * 2 + 1][0] = q2; b_hi[nh * 2 + 1][1] = q3;
                ldmx4(base + 49152 + off, q0, q1, q2, q3);
                b_lo[nh * 2][0] = q0; b_lo[nh * 2][1] = q1;
                b_lo[nh * 2 + 1][0] = q2; b_lo[nh * 2 + 1][1] = q3;
            }
#pragma unroll
            for (int mi = 0; mi < 4; mi++)
#pragma unroll
                for (int ni = 0; ni < 4; ni++) {
                    mma_bf16(acc[mi][ni], a_hi[mi], b_hi[ni]);
                    mma_bf16(acc[mi][ni], a_lo[mi], b_hi[ni]);
                    mma_bf16(acc[mi][ni], a_hi[mi], b_lo[ni]);
                }
        }
        if (c + 1 < NCHUNK) {
            store_chunk(st, smem + ((c + 1) & 1) * BUF_SZ, tid);
            __syncthreads();
        }
    }

    // ---- epilogue: bias + deg*cb + relu, store ----
#pragma unroll
    for (int mi = 0; mi < 4; mi++) {
        int row0 = m0 + wm + mi * 16 + g;
        int row1 = row0 + 8;
        float d0 = (row0 < N_NODES) ? g_deg[row0] : 0.f;
        float d1 = (row1 < N_NODES) ? g_deg[row1] : 0.f;
#pragma unroll
        for (int ni = 0; ni < 4; ni++) {
            int cn = wn + ni * 8 + t * 2;
            float2 bs = *(const float2*)(Wsb + cn);
            float2 cb = *(const float2*)(g_cb + cn);
            if (row0 < N_NODES) {
                float2 o;
                o.x = fmaxf(acc[mi][ni][0] + bs.x + d0 * cb.x, 0.f);
                o.y = fmaxf(acc[mi][ni][1] + bs.y + d0 * cb.y, 0.f);
                *(float2*)(out + (size_t)row0 * OUT_CH + cn) = o;
            }
            if (row1 < N_NODES) {
                float2 o;
                o.x = fmaxf(acc[mi][ni][2] + bs.x + d1 * cb.x, 0.f);
                o.y = fmaxf(acc[mi][ni][3] + bs.y + d1 * cb.y, 0.f);
                *(float2*)(out + (size_t)row1 * OUT_CH + cn) = o;
            }
        }
    }
}

// ---------------- launcher ----------------
extern "C" void kernel_launch(void* const* d_in, const int* in_sizes, int n_in,
                              void* d_out, int out_size) {
    const float* x = nullptr; const void* ei = nullptr; const float* tf = nullptr;
    const float* Wsw = nullptr; const float* Wsb = nullptr;
    const float* Wtw = nullptr; const float* Wtb = nullptr;
    const float* Tw = nullptr;  const float* Tb = nullptr;
    int n16384 = 0, n128 = 0;
    for (int i = 0; i < n_in; i++) {
        long long s = in_sizes[i];
        void* p = d_in[i];
        if (s == (long long)N_NODES * IN_CH)      x  = (const float*)p;
        else if (s == 2LL * N_EDGES)              ei = (const void*)p;
        else if (s == (long long)N_EDGES * T_DIM) tf = (const float*)p;
        else if (s == OUT_CH * T_DIM)             Tw = (const float*)p;
        else if (s == OUT_CH * IN_CH) {
            if (n16384++ == 0) Wsw = (const float*)p; else Wtw = (const float*)p;
        } else if (s == OUT_CH) {
            if (n128 == 0) Wsb = (const float*)p;
            else if (n128 == 1) Wtb = (const float*)p;
            else Tb = (const float*)p;
            n128++;
        }
    }
    float* out = (float*)d_out;

    cudaFuncSetAttribute(gemm_mma_kernel,
                         cudaFuncAttributeMaxDynamicSharedMemorySize, SMEM_SZ);

    detect_kernel<<<1, 256>>>((const int*)ei);
    prep_kernel<<<1, 128>>>(Wtb, Tb);
    zero_kernel<<<2048, 256>>>();
    edge_x_kernel<<<N_EDGES / 64, 256>>>(ei, x);   // 8 edges/warp, 8 warps/block
    edge_t_kernel<<<N_EDGES / 64, 256>>>(ei, tf);  // 8 edges/warp
    gemm_mma_kernel<<<(N_NODES + 127) / 128, 256, SMEM_SZ>>>(x, Wsw, Wtw, Tw, Wsb, out);
}